// round 7
// baseline (speedup 1.0000x reference)
#include <cuda_runtime.h>
#include <cstdint>

#define BATCH 16
#define NROW  196
#define CDIM  768
#define HDIM  512
#define ODIM  128
#define MTOT  (BATCH * NROW)   // 3136

#define TM 128
#define TN 64
#define TK 16
#define NTHREADS 128
#define MTILES ((MTOT + TM - 1) / TM)   // 25
#define NTILES (HDIM / TN)              // 8
#define NKT (CDIM / TK)                 // 48

// Scratch: s[which][b][h] = sum_i relu( x_which[b,i,:] . W_which[:,h] )
__device__ float g_s[2][BATCH][HDIM];

// ---------------- f32x2 helpers ----------------

__device__ __forceinline__ void ffma2(unsigned long long& d, unsigned long long a,
                                      unsigned long long b) {
    asm("fma.rn.f32x2 %0, %1, %2, %0;" : "+l"(d) : "l"(a), "l"(b));
}

__device__ __forceinline__ unsigned long long dup2(float w) {
    unsigned long long r;
    uint32_t u = __float_as_uint(w);
    asm("mov.b64 %0, {%1, %1};" : "=l"(r) : "r"(u));
    return r;
}

__device__ __forceinline__ void unpack2(unsigned long long v, float& lo, float& hi) {
    uint32_t l_, h_;
    asm("mov.b64 {%0, %1}, %2;" : "=r"(l_), "=r"(h_) : "l"(v));
    lo = __uint_as_float(l_);
    hi = __uint_as_float(h_);
}

// ---------------- kernels ----------------

__global__ void zero_s_kernel() {
    int i = blockIdx.x * 256 + threadIdx.x;
    float* p = &g_s[0][0][0];
    if (i < 2 * BATCH * HDIM) p[i] = 0.0f;
}

// GEMM [3136,768] x [768,512] with ReLU + per-batch row-sum epilogue.
// f32x2 packed math, double-buffered smem, one barrier per K-tile.
__global__ __launch_bounds__(NTHREADS, 4)
void gemm_relu_rowsum_f32x2(const float* __restrict__ x1,
                            const float* __restrict__ x2,
                            const float* __restrict__ W1,
                            const float* __restrict__ W2) {
    const int which = blockIdx.z;
    const float* __restrict__ X = which ? x2 : x1;
    const float* __restrict__ W = which ? W2 : W1;

    const int m0 = blockIdx.x * TM;
    const int n0 = blockIdx.y * TN;
    const int tid = threadIdx.x;
    const int tr = tid >> 3;   // 0..15 : row group (8 rows each)
    const int tc = tid & 7;    // 0..7  : col group (8 cols each)

    __shared__ float Xs[2][TK][TM];                  // 2 x 8 KB
    __shared__ unsigned long long Wd[2][TK][TN];     // 2 x 8 KB, dup-pair permuted
    // Wd slot for logical col n (0..63): slot = ((n&7)>>1)*16 + (n>>3)*2 + (n&1)

    unsigned long long acc[4][8];   // [m-pair][n]
#pragma unroll
    for (int i = 0; i < 4; i++)
#pragma unroll
        for (int j = 0; j < 8; j++) acc[i][j] = 0ull;

    const int xrow = m0 + tid;            // each thread owns one X row per tile
    const bool xvalid = (xrow < MTOT);
    const float* xbase = X + (size_t)xrow * CDIM;
    const int widx0 = tid * 2;            // W: 1024 floats = 256 float4

    // ---- prefetch K-tile 0 ----
    float4 xv[4], wv[2];
#pragma unroll
    for (int q = 0; q < 4; q++)
        xv[q] = xvalid ? ((const float4*)xbase)[q] : make_float4(0.f, 0.f, 0.f, 0.f);
#pragma unroll
    for (int i = 0; i < 2; i++) {
        int idx = widx0 + i;
        wv[i] = *(const float4*)(W + (size_t)(idx >> 4) * HDIM + n0 + (idx & 15) * 4);
    }

    for (int kt = 0; kt < NKT; kt++) {
        const int buf = kt & 1;

        // ---- store prefetched tile to smem buffer `buf` ----
#pragma unroll
        for (int q = 0; q < 4; q++) {
            Xs[buf][q * 4 + 0][tid] = xv[q].x;
            Xs[buf][q * 4 + 1][tid] = xv[q].y;
            Xs[buf][q * 4 + 2][tid] = xv[q].z;
            Xs[buf][q * 4 + 3][tid] = xv[q].w;
        }
#pragma unroll
        for (int i = 0; i < 2; i++) {
            int idx = widx0 + i;
            int r = idx >> 4;
            int c4 = idx & 15;
            float vals[4] = {wv[i].x, wv[i].y, wv[i].z, wv[i].w};
#pragma unroll
            for (int q = 0; q < 4; q++) {
                int n = c4 * 4 + q;
                int slot = ((n & 7) >> 1) * 16 + (n >> 3) * 2 + (n & 1);
                Wd[buf][r][slot] = dup2(vals[q]);
            }
        }

        // ---- prefetch K-tile kt+1 (LDG hides under this tile's compute) ----
        if (kt + 1 < NKT) {
            const int k0n = (kt + 1) * TK;
#pragma unroll
            for (int q = 0; q < 4; q++)
                xv[q] = xvalid ? *(const float4*)(xbase + k0n + q * 4)
                               : make_float4(0.f, 0.f, 0.f, 0.f);
#pragma unroll
            for (int i = 0; i < 2; i++) {
                int idx = widx0 + i;
                wv[i] = *(const float4*)(W + (size_t)(k0n + (idx >> 4)) * HDIM +
                                         n0 + (idx & 15) * 4);
            }
        }

        __syncthreads();   // buffer `buf` fully stored (other buffer untouched)

        // ---- compute from buffer `buf`: per k, 6 LDS.128 + 32 FFMA2 ----
#pragma unroll
        for (int kk = 0; kk < TK; kk++) {
            unsigned long long a2[4], b2[8];
            {
                double2 t0 = *(const double2*)&Xs[buf][kk][tr * 8];
                double2 t1 = *(const double2*)&Xs[buf][kk][tr * 8 + 4];
                a2[0] = __double_as_longlong(t0.x);
                a2[1] = __double_as_longlong(t0.y);
                a2[2] = __double_as_longlong(t1.x);
                a2[3] = __double_as_longlong(t1.y);
            }
#pragma unroll
            for (int p = 0; p < 4; p++) {
                double2 t = *(const double2*)&Wd[buf][kk][p * 16 + tc * 2];
                b2[2 * p]     = __double_as_longlong(t.x);
                b2[2 * p + 1] = __double_as_longlong(t.y);
            }
#pragma unroll
            for (int i = 0; i < 4; i++)
#pragma unroll
                for (int j = 0; j < 8; j++)
                    ffma2(acc[i][j], a2[i], b2[j]);
        }
        // no second barrier: next iteration stores to the other buffer, and
        // sync(kt+1) can only be reached after every warp finished compute(kt).
    }

    // ---- unpack to scalar 8x8 ----
    float accf[8][8];
#pragma unroll
    for (int i = 0; i < 4; i++)
#pragma unroll
        for (int j = 0; j < 8; j++)
            unpack2(acc[i][j], accf[2 * i][j], accf[2 * i + 1][j]);

    // ---- epilogue: relu, group rows by batch, atomic into g_s ----
    const int rowbase = m0 + tr * 8;
    const int colbase = n0 + tc * 8;

    int i = 0;
    while (i < 8) {
        int gr = rowbase + i;
        if (gr >= MTOT) break;
        int b = gr / NROW;
        int bend = (b + 1) * NROW;
        float cs[8];
#pragma unroll
        for (int j = 0; j < 8; j++) cs[j] = 0.0f;
        while (i < 8 && (rowbase + i) < bend && (rowbase + i) < MTOT) {
#pragma unroll
            for (int j = 0; j < 8; j++) cs[j] += fmaxf(accf[i][j], 0.0f);
            i++;
        }
        float* dst = &g_s[which][b][colbase];
#pragma unroll
        for (int j = 0; j < 8; j++) atomicAdd(dst + j, cs[j]);
    }
}

// out[b,o] = sum_h s1[b,h]*s2[b,h]*Wp[h,o] + bp[o]*N1*N2
__global__ __launch_bounds__(ODIM)
void final_kernel(const float* __restrict__ Wp,
                  const float* __restrict__ bp,
                  float* __restrict__ out) {
    const int b = blockIdx.x;
    const int o = threadIdx.x;

    __shared__ float sprod[HDIM];
    for (int h = o; h < HDIM; h += ODIM)
        sprod[h] = g_s[0][b][h] * g_s[1][b][h];
    __syncthreads();

    float acc = 0.0f;
#pragma unroll 8
    for (int h = 0; h < HDIM; h++)
        acc = fmaf(sprod[h], Wp[(size_t)h * ODIM + o], acc);

    out[b * ODIM + o] = acc + bp[o] * (float)(NROW * NROW);
}

extern "C" void kernel_launch(void* const* d_in, const int* in_sizes, int n_in,
                              void* d_out, int out_size) {
    const float* x1 = (const float*)d_in[0];
    const float* x2 = (const float*)d_in[1];
    const float* W1 = (const float*)d_in[2];
    const float* W2 = (const float*)d_in[3];
    const float* Wp = (const float*)d_in[4];
    const float* bp = (const float*)d_in[5];
    float* out = (float*)d_out;

    zero_s_kernel<<<(2 * BATCH * HDIM + 255) / 256, 256>>>();
    gemm_relu_rowsum_f32x2<<<dim3(MTILES, NTILES, 2), NTHREADS>>>(x1, x2, W1, W2);
    final_kernel<<<BATCH, ODIM>>>(Wp, bp, out);
}

// round 9
// speedup vs baseline: 1.0707x; 1.0707x over previous
#include <cuda_runtime.h>
#include <cstdint>

#define BATCH 16
#define NROW  196
#define CDIM  768
#define HDIM  512
#define ODIM  128
#define MTOT  (BATCH * NROW)   // 3136

#define TM 128
#define TN 64
#define TK 16
#define NTHREADS 128
#define MTILES ((MTOT + TM - 1) / TM)   // 25
#define NTILES (HDIM / TN)              // 8
#define NKT (CDIM / TK)                 // 48

// Scratch: s[which][b][h] = sum_i relu( x_which[b,i,:] . W_which[:,h] )
__device__ float g_s[2][BATCH][HDIM];

// ---------------- f32x2 helpers ----------------

__device__ __forceinline__ void ffma2(unsigned long long& d, unsigned long long a,
                                      unsigned long long b) {
    asm("fma.rn.f32x2 %0, %1, %2, %0;" : "+l"(d) : "l"(a), "l"(b));
}

__device__ __forceinline__ unsigned long long dup2(float w) {
    unsigned long long r;
    uint32_t u = __float_as_uint(w);
    asm("mov.b64 %0, {%1, %1};" : "=l"(r) : "r"(u));
    return r;
}

__device__ __forceinline__ void unpack2(unsigned long long v, float& lo, float& hi) {
    uint32_t l_, h_;
    asm("mov.b64 {%0, %1}, %2;" : "=r"(l_), "=r"(h_) : "l"(v));
    lo = __uint_as_float(l_);
    hi = __uint_as_float(h_);
}

// ---------------- kernels ----------------

__global__ void zero_s_kernel() {
    int i = blockIdx.x * 256 + threadIdx.x;
    float* p = &g_s[0][0][0];
    if (i < 2 * BATCH * HDIM) p[i] = 0.0f;
}

// GEMM [3136,768] x [768,512] with ReLU + per-batch row-sum epilogue.
// f32x2 packed along n: A operand dup'd in registers (ALU pipe), W smem is
// plain f32 -> minimal crossbar traffic. Double-buffered smem, 1 barrier/tile.
__global__ __launch_bounds__(NTHREADS, 3)
void gemm_relu_rowsum_f32x2(const float* __restrict__ x1,
                            const float* __restrict__ x2,
                            const float* __restrict__ W1,
                            const float* __restrict__ W2) {
    const int which = blockIdx.z;
    const float* __restrict__ X = which ? x2 : x1;
    const float* __restrict__ W = which ? W2 : W1;

    const int m0 = blockIdx.x * TM;
    const int n0 = blockIdx.y * TN;
    const int tid = threadIdx.x;
    const int tr = tid >> 3;   // 0..15 : row group (8 rows each)
    const int tc = tid & 7;    // 0..7  : col group (8 cols each)

    __shared__ float Xs[2][TK][TM];   // 2 x 8 KB : Xs[k][row]
    __shared__ float Ws[2][TK][TN];   // 2 x 4 KB : Ws[k][col], plain f32

    unsigned long long acc[8][4];     // [m][n-pair]
#pragma unroll
    for (int i = 0; i < 8; i++)
#pragma unroll
        for (int p = 0; p < 4; p++) acc[i][p] = 0ull;

    const int xrow = m0 + tid;            // each thread owns one X row per tile
    const bool xvalid = (xrow < MTOT);
    const float* xbase = X + (size_t)xrow * CDIM;
    const int widx0 = tid * 2;            // W: 1024 floats = 256 float4

    // ---- prefetch K-tile 0 ----
    float4 xv[4], wv[2];
#pragma unroll
    for (int q = 0; q < 4; q++)
        xv[q] = xvalid ? ((const float4*)xbase)[q] : make_float4(0.f, 0.f, 0.f, 0.f);
#pragma unroll
    for (int i = 0; i < 2; i++) {
        int idx = widx0 + i;
        wv[i] = *(const float4*)(W + (size_t)(idx >> 4) * HDIM + n0 + (idx & 15) * 4);
    }

    for (int kt = 0; kt < NKT; kt++) {
        const int buf = kt & 1;

        // ---- store prefetched tile to smem buffer `buf` ----
#pragma unroll
        for (int q = 0; q < 4; q++) {
            Xs[buf][q * 4 + 0][tid] = xv[q].x;
            Xs[buf][q * 4 + 1][tid] = xv[q].y;
            Xs[buf][q * 4 + 2][tid] = xv[q].z;
            Xs[buf][q * 4 + 3][tid] = xv[q].w;
        }
#pragma unroll
        for (int i = 0; i < 2; i++) {
            int idx = widx0 + i;
            *(float4*)&Ws[buf][idx >> 4][(idx & 15) * 4] = wv[i];
        }

        // ---- prefetch K-tile kt+1 (LDG hides under this tile's compute) ----
        if (kt + 1 < NKT) {
            const int k0n = (kt + 1) * TK;
#pragma unroll
            for (int q = 0; q < 4; q++)
                xv[q] = xvalid ? *(const float4*)(xbase + k0n + q * 4)
                               : make_float4(0.f, 0.f, 0.f, 0.f);
#pragma unroll
            for (int i = 0; i < 2; i++) {
                int idx = widx0 + i;
                wv[i] = *(const float4*)(W + (size_t)(k0n + (idx >> 4)) * HDIM +
                                         n0 + (idx & 15) * 4);
            }
        }

        __syncthreads();   // buffer `buf` fully stored (other buffer untouched)

        // ---- compute: per k, 4 LDS.128 + 8 dup movs (ALU) + 32 FFMA2 ----
#pragma unroll
        for (int kk = 0; kk < TK; kk++) {
            float4 xa = *(const float4*)&Xs[buf][kk][tr * 8];
            float4 xb = *(const float4*)&Xs[buf][kk][tr * 8 + 4];
            unsigned long long a2[8];
            a2[0] = dup2(xa.x); a2[1] = dup2(xa.y);
            a2[2] = dup2(xa.z); a2[3] = dup2(xa.w);
            a2[4] = dup2(xb.x); a2[5] = dup2(xb.y);
            a2[6] = dup2(xb.z); a2[7] = dup2(xb.w);

            unsigned long long b2[4];
            {
                double2 t0 = *(const double2*)&Ws[buf][kk][tc * 8];
                double2 t1 = *(const double2*)&Ws[buf][kk][tc * 8 + 4];
                b2[0] = __double_as_longlong(t0.x);
                b2[1] = __double_as_longlong(t0.y);
                b2[2] = __double_as_longlong(t1.x);
                b2[3] = __double_as_longlong(t1.y);
            }
#pragma unroll
            for (int i = 0; i < 8; i++)
#pragma unroll
                for (int p = 0; p < 4; p++)
                    ffma2(acc[i][p], a2[i], b2[p]);
        }
        // no second barrier: next iter stores to the other buffer; sync(kt+1)
        // is only reached after every warp finished compute(kt).
    }

    // ---- unpack to scalar 8x8 (cols are natural pairs) ----
    float accf[8][8];
#pragma unroll
    for (int i = 0; i < 8; i++)
#pragma unroll
        for (int p = 0; p < 4; p++)
            unpack2(acc[i][p], accf[i][2 * p], accf[i][2 * p + 1]);

    // ---- epilogue: relu, group rows by batch, atomic into g_s ----
    const int rowbase = m0 + tr * 8;
    const int colbase = n0 + tc * 8;

    int i = 0;
    while (i < 8) {
        int gr = rowbase + i;
        if (gr >= MTOT) break;
        int b = gr / NROW;
        int bend = (b + 1) * NROW;
        float cs[8];
#pragma unroll
        for (int j = 0; j < 8; j++) cs[j] = 0.0f;
        while (i < 8 && (rowbase + i) < bend && (rowbase + i) < MTOT) {
#pragma unroll
            for (int j = 0; j < 8; j++) cs[j] += fmaxf(accf[i][j], 0.0f);
            i++;
        }
        float* dst = &g_s[which][b][colbase];
#pragma unroll
        for (int j = 0; j < 8; j++) atomicAdd(dst + j, cs[j]);
    }
}

// out[b,o] = sum_h s1[b,h]*s2[b,h]*Wp[h,o] + bp[o]*N1*N2
__global__ __launch_bounds__(ODIM)
void final_kernel(const float* __restrict__ Wp,
                  const float* __restrict__ bp,
                  float* __restrict__ out) {
    const int b = blockIdx.x;
    const int o = threadIdx.x;

    __shared__ float sprod[HDIM];
    for (int h = o; h < HDIM; h += ODIM)
        sprod[h] = g_s[0][b][h] * g_s[1][b][h];
    __syncthreads();

    float acc = 0.0f;
#pragma unroll 8
    for (int h = 0; h < HDIM; h++)
        acc = fmaf(sprod[h], Wp[(size_t)h * ODIM + o], acc);

    out[b * ODIM + o] = acc + bp[o] * (float)(NROW * NROW);
}

extern "C" void kernel_launch(void* const* d_in, const int* in_sizes, int n_in,
                              void* d_out, int out_size) {
    const float* x1 = (const float*)d_in[0];
    const float* x2 = (const float*)d_in[1];
    const float* W1 = (const float*)d_in[2];
    const float* W2 = (const float*)d_in[3];
    const float* Wp = (const float*)d_in[4];
    const float* bp = (const float*)d_in[5];
    float* out = (float*)d_out;

    zero_s_kernel<<<(2 * BATCH * HDIM + 255) / 256, 256>>>();
    gemm_relu_rowsum_f32x2<<<dim3(MTILES, NTILES, 2), NTHREADS>>>(x1, x2, W1, W2);
    final_kernel<<<BATCH, ODIM>>>(Wp, bp, out);
}

// round 13
// speedup vs baseline: 1.1245x; 1.0503x over previous
#include <cuda_runtime.h>
#include <cstdint>

#define BATCH 16
#define NROW  196
#define CDIM  768
#define HDIM  512
#define ODIM  128
#define MTOT  (BATCH * NROW)   // 3136

#define TM 128
#define TN 64
#define TK 32
#define NTHREADS 128
#define MTILES ((MTOT + TM - 1) / TM)   // 25
#define NTILES (HDIM / TN)              // 8
#define NKT (CDIM / TK)                 // 24

// Scratch: s[which][b][h] = sum_i relu( x_which[b,i,:] . W_which[:,h] )
__device__ float g_s[2][BATCH][HDIM];

// ---------------- helpers ----------------

__device__ __forceinline__ uint32_t smem_u32(const void* p) {
    uint32_t a;
    asm("{ .reg .u64 t; cvta.to.shared.u64 t, %1; cvt.u32.u64 %0, t; }" : "=r"(a) : "l"(p));
    return a;
}

__device__ __forceinline__ void cp_async16(uint32_t dst, const void* src) {
    asm volatile("cp.async.cg.shared.global [%0], [%1], 16;" :: "r"(dst), "l"(src) : "memory");
}
__device__ __forceinline__ void cp_async_commit() {
    asm volatile("cp.async.commit_group;" ::: "memory");
}
__device__ __forceinline__ void cp_async_wait0() {
    asm volatile("cp.async.wait_group 0;" ::: "memory");
}

__device__ __forceinline__ void ffma2(unsigned long long& d, unsigned long long a,
                                      unsigned long long b) {
    asm("fma.rn.f32x2 %0, %1, %2, %0;" : "+l"(d) : "l"(a), "l"(b));
}

__device__ __forceinline__ unsigned long long dup2(float w) {
    unsigned long long r;
    uint32_t u = __float_as_uint(w);
    asm("mov.b64 %0, {%1, %1};" : "=l"(r) : "r"(u));
    return r;
}

__device__ __forceinline__ void unpack2(unsigned long long v, float& lo, float& hi) {
    uint32_t l_, h_;
    asm("mov.b64 {%0, %1}, %2;" : "=r"(l_), "=r"(h_) : "l"(v));
    lo = __uint_as_float(l_);
    hi = __uint_as_float(h_);
}

// ---------------- kernels ----------------

__global__ void zero_s_kernel() {
    int i = blockIdx.x * 256 + threadIdx.x;
    float* p = &g_s[0][0][0];
    if (i < 2 * BATCH * HDIM) p[i] = 0.0f;
}

// GEMM [3136,768] x [768,512] with ReLU + per-batch row-sum epilogue.
// f32x2 packed along n; TK=32 (24 epochs); X register-staged (transpose),
// W via cp.async (layout already matches gmem); double-buffered, 1 barrier/tile.
__global__ __launch_bounds__(NTHREADS, 3)
void gemm_relu_rowsum_f32x2(const float* __restrict__ x1,
                            const float* __restrict__ x2,
                            const float* __restrict__ W1,
                            const float* __restrict__ W2) {
    const int which = blockIdx.z;
    const float* __restrict__ X = which ? x2 : x1;
    const float* __restrict__ W = which ? W2 : W1;

    const int m0 = blockIdx.x * TM;
    const int n0 = blockIdx.y * TN;
    const int tid = threadIdx.x;
    const int tr = tid >> 3;   // 0..15 : row group (8 rows each)
    const int tc = tid & 7;    // 0..7  : col group (8 cols each)

    __shared__ float Xs[2][TK][TM];   // 2 x 16 KB : Xs[k][row] (transposed)
    __shared__ float Ws[2][TK][TN];   // 2 x  8 KB : Ws[k][col] (gmem layout)

    unsigned long long acc[8][4];     // [m][n-pair]
#pragma unroll
    for (int i = 0; i < 8; i++)
#pragma unroll
        for (int p = 0; p < 4; p++) acc[i][p] = 0ull;

    const int xrow = m0 + tid;            // each thread owns one X row per tile
    const bool xvalid = (xrow < MTOT);
    const float* xbase = X + (size_t)xrow * CDIM;

    // W tile: 32k x 64n = 512 float4; this thread copies ops o = tid + q*128.
    // Precompute per-op (k, n4):
    //   k = o >> 4, n4 = (o & 15) * 4
    // ---- prologue: cp.async W tile 0 -> Ws[0]; register prefetch X tile 0 ----
#pragma unroll
    for (int q = 0; q < 4; q++) {
        int o = tid + q * NTHREADS;
        int k = o >> 4, n4 = (o & 15) * 4;
        cp_async16(smem_u32(&Ws[0][k][n4]), W + (size_t)k * HDIM + n0 + n4);
    }
    cp_async_commit();

    float4 xv[8];
#pragma unroll
    for (int q = 0; q < 8; q++)
        xv[q] = xvalid ? ((const float4*)xbase)[q] : make_float4(0.f, 0.f, 0.f, 0.f);

    for (int kt = 0; kt < NKT; kt++) {
        const int buf = kt & 1;

        // ---- store X tile kt into Xs[buf] (transposed) ----
#pragma unroll
        for (int q = 0; q < 8; q++) {
            Xs[buf][q * 4 + 0][tid] = xv[q].x;
            Xs[buf][q * 4 + 1][tid] = xv[q].y;
            Xs[buf][q * 4 + 2][tid] = xv[q].z;
            Xs[buf][q * 4 + 3][tid] = xv[q].w;
        }

        // ---- register prefetch X tile kt+1 ----
        if (kt + 1 < NKT) {
            const int k0n = (kt + 1) * TK;
#pragma unroll
            for (int q = 0; q < 8; q++)
                xv[q] = xvalid ? *(const float4*)(xbase + k0n + q * 4)
                               : make_float4(0.f, 0.f, 0.f, 0.f);
        }

        cp_async_wait0();     // W tile kt has landed in Ws[buf]
        __syncthreads();      // all warps past compute(kt-1); both buffers settled

        // ---- issue cp.async W tile kt+1 into Ws[buf^1] (overlaps compute) ----
        if (kt + 1 < NKT) {
            const int k0n = (kt + 1) * TK;
#pragma unroll
            for (int q = 0; q < 4; q++) {
                int o = tid + q * NTHREADS;
                int k = o >> 4, n4 = (o & 15) * 4;
                cp_async16(smem_u32(&Ws[buf ^ 1][k][n4]),
                           W + (size_t)(k0n + k) * HDIM + n0 + n4);
            }
            cp_async_commit();
        }

        // ---- compute: per k, 4 LDS.128 + 8 dup movs (ALU) + 32 FFMA2 ----
#pragma unroll 4
        for (int kk = 0; kk < TK; kk++) {
            float4 xa = *(const float4*)&Xs[buf][kk][tr * 8];
            float4 xb = *(const float4*)&Xs[buf][kk][tr * 8 + 4];
            unsigned long long a2[8];
            a2[0] = dup2(xa.x); a2[1] = dup2(xa.y);
            a2[2] = dup2(xa.z); a2[3] = dup2(xa.w);
            a2[4] = dup2(xb.x); a2[5] = dup2(xb.y);
            a2[6] = dup2(xb.z); a2[7] = dup2(xb.w);

            unsigned long long b2[4];
            {
                double2 t0 = *(const double2*)&Ws[buf][kk][tc * 8];
                double2 t1 = *(const double2*)&Ws[buf][kk][tc * 8 + 4];
                b2[0] = __double_as_longlong(t0.x);
                b2[1] = __double_as_longlong(t0.y);
                b2[2] = __double_as_longlong(t1.x);
                b2[3] = __double_as_longlong(t1.y);
            }
#pragma unroll
            for (int i = 0; i < 8; i++)
#pragma unroll
                for (int p = 0; p < 4; p++)
                    ffma2(acc[i][p], a2[i], b2[p]);
        }
        // next iteration's barrier orders everything before buffer reuse.
    }

    // ---- unpack to scalar 8x8 (cols are natural pairs) ----
    float accf[8][8];
#pragma unroll
    for (int i = 0; i < 8; i++)
#pragma unroll
        for (int p = 0; p < 4; p++)
            unpack2(acc[i][p], accf[i][2 * p], accf[i][2 * p + 1]);

    // ---- epilogue: relu, group rows by batch, atomic into g_s ----
    const int rowbase = m0 + tr * 8;
    const int colbase = n0 + tc * 8;

    int i = 0;
    while (i < 8) {
        int gr = rowbase + i;
        if (gr >= MTOT) break;
        int b = gr / NROW;
        int bend = (b + 1) * NROW;
        float cs[8];
#pragma unroll
        for (int j = 0; j < 8; j++) cs[j] = 0.0f;
        while (i < 8 && (rowbase + i) < bend && (rowbase + i) < MTOT) {
#pragma unroll
            for (int j = 0; j < 8; j++) cs[j] += fmaxf(accf[i][j], 0.0f);
            i++;
        }
        float* dst = &g_s[which][b][colbase];
#pragma unroll
        for (int j = 0; j < 8; j++) atomicAdd(dst + j, cs[j]);
    }
}

// out[b,o] = sum_h s1[b,h]*s2[b,h]*Wp[h,o] + bp[o]*N1*N2
__global__ __launch_bounds__(ODIM)
void final_kernel(const float* __restrict__ Wp,
                  const float* __restrict__ bp,
                  float* __restrict__ out) {
    const int b = blockIdx.x;
    const int o = threadIdx.x;

    __shared__ float sprod[HDIM];
    for (int h = o; h < HDIM; h += ODIM)
        sprod[h] = g_s[0][b][h] * g_s[1][b][h];
    __syncthreads();

    float acc = 0.0f;
#pragma unroll 8
    for (int h = 0; h < HDIM; h++)
        acc = fmaf(sprod[h], Wp[(size_t)h * ODIM + o], acc);

    out[b * ODIM + o] = acc + bp[o] * (float)(NROW * NROW);
}

extern "C" void kernel_launch(void* const* d_in, const int* in_sizes, int n_in,
                              void* d_out, int out_size) {
    const float* x1 = (const float*)d_in[0];
    const float* x2 = (const float*)d_in[1];
    const float* W1 = (const float*)d_in[2];
    const float* W2 = (const float*)d_in[3];
    const float* Wp = (const float*)d_in[4];
    const float* bp = (const float*)d_in[5];
    float* out = (float*)d_out;

    zero_s_kernel<<<(2 * BATCH * HDIM + 255) / 256, 256>>>();
    gemm_relu_rowsum_f32x2<<<dim3(MTILES, NTILES, 2), NTHREADS>>>(x1, x2, W1, W2);
    final_kernel<<<BATCH, ODIM>>>(Wp, bp, out);
}

// round 14
// speedup vs baseline: 1.2092x; 1.0753x over previous
#include <cuda_runtime.h>
#include <cstdint>

#define BATCH 16
#define NROW  196
#define CDIM  768
#define HDIM  512
#define ODIM  128
#define MTOT  (BATCH * NROW)   // 3136

#define TM 128
#define TN 64
#define TK 32
#define XPAD 36                 // floats per Xs row: 144B, 16B-aligned, bank-safe
#define NTHREADS 128
#define MTILES ((MTOT + TM - 1) / TM)   // 25
#define NTILES (HDIM / TN)              // 8
#define NKT (CDIM / TK)                 // 24

#define XS_BYTES (TM * XPAD * 4)            // 18432
#define WS_BYTES (TK * TN * 4)              // 8192
#define SMEM_SZ  (2 * XS_BYTES + 2 * WS_BYTES)   // 53248

// Scratch: s[which][b][h] = sum_i relu( x_which[b,i,:] . W_which[:,h] )
// Zero-initialized at module load; final_kernel re-zeros after each use.
__device__ float g_s[2][BATCH][HDIM];

// ---------------- helpers ----------------

__device__ __forceinline__ uint32_t smem_u32(const void* p) {
    uint32_t a;
    asm("{ .reg .u64 t; cvta.to.shared.u64 t, %1; cvt.u32.u64 %0, t; }" : "=r"(a) : "l"(p));
    return a;
}

__device__ __forceinline__ void cp_async16(uint32_t dst, const void* src) {
    asm volatile("cp.async.cg.shared.global [%0], [%1], 16;" :: "r"(dst), "l"(src) : "memory");
}
// cp-size 16, src-size var: src bytes copied, remainder zero-filled (0 = all zeros)
__device__ __forceinline__ void cp_async16_zfill(uint32_t dst, const void* src, int srcsz) {
    asm volatile("cp.async.cg.shared.global [%0], [%1], 16, %2;"
                 :: "r"(dst), "l"(src), "r"(srcsz) : "memory");
}
__device__ __forceinline__ void cp_async_commit() {
    asm volatile("cp.async.commit_group;" ::: "memory");
}
__device__ __forceinline__ void cp_async_wait0() {
    asm volatile("cp.async.wait_group 0;" ::: "memory");
}

__device__ __forceinline__ void ffma2(unsigned long long& d, unsigned long long a,
                                      unsigned long long b) {
    asm("fma.rn.f32x2 %0, %1, %2, %0;" : "+l"(d) : "l"(a), "l"(b));
}

__device__ __forceinline__ unsigned long long dup2(float w) {
    unsigned long long r;
    uint32_t u = __float_as_uint(w);
    asm("mov.b64 %0, {%1, %1};" : "=l"(r) : "r"(u));
    return r;
}

__device__ __forceinline__ void unpack2(unsigned long long v, float& lo, float& hi) {
    uint32_t l_, h_;
    asm("mov.b64 {%0, %1}, %2;" : "=r"(l_), "=r"(h_) : "l"(v));
    lo = __uint_as_float(l_);
    hi = __uint_as_float(h_);
}

// ---------------- kernels ----------------

// GEMM [3136,768] x [768,512] with ReLU + per-batch row-sum epilogue.
// Both X and W tiles via cp.async (no register staging, no STS phase).
// Xs padded row-major [row][36]: scalar A loads are conflict-free (4 distinct
// banks, 8-lane broadcast). f32x2 packed along n. Double-buffered, 1 barrier/tile.
__global__ __launch_bounds__(NTHREADS, 3)
void gemm_relu_rowsum_f32x2(const float* __restrict__ x1,
                            const float* __restrict__ x2,
                            const float* __restrict__ W1,
                            const float* __restrict__ W2) {
    extern __shared__ char smem[];
    float (*Xs)[TM][XPAD] = (float (*)[TM][XPAD])smem;                  // [2][128][36]
    float (*Ws)[TK][TN]   = (float (*)[TK][TN])(smem + 2 * XS_BYTES);   // [2][32][64]

    const int which = blockIdx.z;
    const float* __restrict__ X = which ? x2 : x1;
    const float* __restrict__ W = which ? W2 : W1;

    const int m0 = blockIdx.x * TM;
    const int n0 = blockIdx.y * TN;
    const int tid = threadIdx.x;
    const int tr = tid >> 3;   // 0..15 : row group (8 rows each)
    const int tc = tid & 7;    // 0..7  : col group (8 cols each)

    unsigned long long acc[8][4];     // [m][n-pair]
#pragma unroll
    for (int i = 0; i < 8; i++)
#pragma unroll
        for (int p = 0; p < 4; p++) acc[i][p] = 0ull;

    // X tile: 128 rows x 32 k = 128B/row = 8 cp.async.16 per row; 1024 ops,
    // thread does o = tid + q*128 (q<8): row = o>>3, chunk = o&7.
    // W tile: 32k x 64n = 512 float4; thread does o = tid + q*128 (q<4):
    // k = o>>4, n4 = (o&15)*4.
    // Per-thread precomputed (constant across kt):
    int xrowl[8], xchk[8];
    const float* xsrc0[8];
    int xsz[8];
#pragma unroll
    for (int q = 0; q < 8; q++) {
        int o = tid + q * NTHREADS;
        xrowl[q] = o >> 3;
        xchk[q] = o & 7;
        int gr = m0 + xrowl[q];
        bool v = gr < MTOT;
        xsrc0[q] = X + (size_t)(v ? gr : 0) * CDIM + xchk[q] * 4;
        xsz[q] = v ? 16 : 0;
    }

    // ---- prologue: cp.async tile 0 (X and W) ----
#pragma unroll
    for (int q = 0; q < 8; q++)
        cp_async16_zfill(smem_u32(&Xs[0][xrowl[q]][xchk[q] * 4]), xsrc0[q], xsz[q]);
#pragma unroll
    for (int q = 0; q < 4; q++) {
        int o = tid + q * NTHREADS;
        int k = o >> 4, n4 = (o & 15) * 4;
        cp_async16(smem_u32(&Ws[0][k][n4]), W + (size_t)k * HDIM + n0 + n4);
    }
    cp_async_commit();

    for (int kt = 0; kt < NKT; kt++) {
        const int buf = kt & 1;

        cp_async_wait0();     // tile kt landed (this thread's copies)
        __syncthreads();      // visible to all; compute(kt-1) finished

        // ---- issue cp.async tile kt+1 into buf^1 (overlaps compute) ----
        if (kt + 1 < NKT) {
            const int k0n = (kt + 1) * TK;
#pragma unroll
            for (int q = 0; q < 8; q++)
                cp_async16_zfill(smem_u32(&Xs[buf ^ 1][xrowl[q]][xchk[q] * 4]),
                                 xsrc0[q] + k0n, xsz[q]);
#pragma unroll
            for (int q = 0; q < 4; q++) {
                int o = tid + q * NTHREADS;
                int k = o >> 4, n4 = (o & 15) * 4;
                cp_async16(smem_u32(&Ws[buf ^ 1][k][n4]),
                           W + (size_t)(k0n + k) * HDIM + n0 + n4);
            }
            cp_async_commit();
        }

        // ---- compute: per k, 8 LDS.32 (A, bank-safe) + 2 LDS.128 (B) + 32 FFMA2 ----
        const float* xr0 = &Xs[buf][tr * 8][0];
#pragma unroll 4
        for (int kk = 0; kk < TK; kk++) {
            unsigned long long a2[8];
#pragma unroll
            for (int i = 0; i < 8; i++)
                a2[i] = dup2(xr0[i * XPAD + kk]);

            unsigned long long b2[4];
            {
                double2 t0 = *(const double2*)&Ws[buf][kk][tc * 8];
                double2 t1 = *(const double2*)&Ws[buf][kk][tc * 8 + 4];
                b2[0] = __double_as_longlong(t0.x);
                b2[1] = __double_as_longlong(t0.y);
                b2[2] = __double_as_longlong(t1.x);
                b2[3] = __double_as_longlong(t1.y);
            }
#pragma unroll
            for (int i = 0; i < 8; i++)
#pragma unroll
                for (int p = 0; p < 4; p++)
                    ffma2(acc[i][p], a2[i], b2[p]);
        }
        // next iteration's barrier orders everything before buffer reuse.
    }

    // ---- unpack to scalar 8x8 (cols are natural pairs) ----
    float accf[8][8];
#pragma unroll
    for (int i = 0; i < 8; i++)
#pragma unroll
        for (int p = 0; p < 4; p++)
            unpack2(acc[i][p], accf[i][2 * p], accf[i][2 * p + 1]);

    // ---- epilogue: relu, group rows by batch, atomic into g_s ----
    const int rowbase = m0 + tr * 8;
    const int colbase = n0 + tc * 8;

    int i = 0;
    while (i < 8) {
        int gr = rowbase + i;
        if (gr >= MTOT) break;
        int b = gr / NROW;
        int bend = (b + 1) * NROW;
        float cs[8];
#pragma unroll
        for (int j = 0; j < 8; j++) cs[j] = 0.0f;
        while (i < 8 && (rowbase + i) < bend && (rowbase + i) < MTOT) {
#pragma unroll
            for (int j = 0; j < 8; j++) cs[j] += fmaxf(accf[i][j], 0.0f);
            i++;
        }
        float* dst = &g_s[which][b][colbase];
#pragma unroll
        for (int j = 0; j < 8; j++) atomicAdd(dst + j, cs[j]);
    }
}

// out[b,o] = sum_h s1[b,h]*s2[b,h]*Wp[h,o] + bp[o]*N1*N2
// Also re-zeros g_s for the next (graph-replayed) call.
__global__ __launch_bounds__(ODIM)
void final_kernel(const float* __restrict__ Wp,
                  const float* __restrict__ bp,
                  float* __restrict__ out) {
    const int b = blockIdx.x;
    const int o = threadIdx.x;

    __shared__ float sprod[HDIM];
    for (int h = o; h < HDIM; h += ODIM) {
        sprod[h] = g_s[0][b][h] * g_s[1][b][h];
        g_s[0][b][h] = 0.0f;   // reset for next launch (this block owns slice b)
        g_s[1][b][h] = 0.0f;
    }
    __syncthreads();

    float acc = 0.0f;
#pragma unroll 8
    for (int h = 0; h < HDIM; h++)
        acc = fmaf(sprod[h], Wp[(size_t)h * ODIM + o], acc);

    out[b * ODIM + o] = acc + bp[o] * (float)(NROW * NROW);
}

extern "C" void kernel_launch(void* const* d_in, const int* in_sizes, int n_in,
                              void* d_out, int out_size) {
    const float* x1 = (const float*)d_in[0];
    const float* x2 = (const float*)d_in[1];
    const float* W1 = (const float*)d_in[2];
    const float* W2 = (const float*)d_in[3];
    const float* Wp = (const float*)d_in[4];
    const float* bp = (const float*)d_in[5];
    float* out = (float*)d_out;

    static bool attr_done = false;
    if (!attr_done) {
        cudaFuncSetAttribute(gemm_relu_rowsum_f32x2,
                             cudaFuncAttributeMaxDynamicSharedMemorySize, SMEM_SZ);
        attr_done = true;
    }

    gemm_relu_rowsum_f32x2<<<dim3(MTILES, NTILES, 2), NTHREADS, SMEM_SZ>>>(x1, x2, W1, W2);
    final_kernel<<<BATCH, ODIM>>>(Wp, bp, out);
}

// round 16
// speedup vs baseline: 1.2998x; 1.0750x over previous
#include <cuda_runtime.h>
#include <cstdint>

#define BATCH 16
#define NROW  196
#define CDIM  768
#define HDIM  512
#define ODIM  128
#define MTOT  (BATCH * NROW)   // 3136

#define TM 128
#define TN 64
#define TK 32
#define XPAD 36                 // floats per Xs row: 144B, 16B-aligned, bank-safe
#define NTHREADS 128
#define MTILES ((MTOT + TM - 1) / TM)   // 25
#define NTILES (HDIM / TN)              // 8
#define NKT (CDIM / TK)                 // 24

#define XS_BYTES (TM * XPAD * 4)            // 18432
#define WS_BYTES (TK * TN * 4)              // 8192
#define SMEM_SZ  (2 * XS_BYTES + 2 * WS_BYTES)   // 53248

// Scratch: s[which][b][h] = sum_i relu( x_which[b,i,:] . W_which[:,h] )
// Zero-initialized at module load; final_kernel re-zeros after each use.
__device__ float g_s[2][BATCH][HDIM];

// ---------------- helpers ----------------

__device__ __forceinline__ uint32_t smem_u32(const void* p) {
    uint32_t a;
    asm("{ .reg .u64 t; cvta.to.shared.u64 t, %1; cvt.u32.u64 %0, t; }" : "=r"(a) : "l"(p));
    return a;
}

__device__ __forceinline__ void cp_async16(uint32_t dst, const void* src) {
    asm volatile("cp.async.cg.shared.global [%0], [%1], 16;" :: "r"(dst), "l"(src) : "memory");
}
// cp-size 16, src-size var: src bytes copied, remainder zero-filled (0 = all zeros)
__device__ __forceinline__ void cp_async16_zfill(uint32_t dst, const void* src, int srcsz) {
    asm volatile("cp.async.cg.shared.global [%0], [%1], 16, %2;"
                 :: "r"(dst), "l"(src), "r"(srcsz) : "memory");
}
__device__ __forceinline__ void cp_async_commit() {
    asm volatile("cp.async.commit_group;" ::: "memory");
}
__device__ __forceinline__ void cp_async_wait0() {
    asm volatile("cp.async.wait_group 0;" ::: "memory");
}

__device__ __forceinline__ void ffma2(unsigned long long& d, unsigned long long a,
                                      unsigned long long b) {
    asm("fma.rn.f32x2 %0, %1, %2, %0;" : "+l"(d) : "l"(a), "l"(b));
}

__device__ __forceinline__ unsigned long long dup2(float w) {
    unsigned long long r;
    uint32_t u = __float_as_uint(w);
    asm("mov.b64 %0, {%1, %1};" : "=l"(r) : "r"(u));
    return r;
}

__device__ __forceinline__ void unpack2(unsigned long long v, float& lo, float& hi) {
    uint32_t l_, h_;
    asm("mov.b64 {%0, %1}, %2;" : "=r"(l_), "=r"(h_) : "l"(v));
    lo = __uint_as_float(l_);
    hi = __uint_as_float(h_);
}

// ---------------- kernels ----------------

// GEMM [3136,768] x [768,512] with ReLU + per-batch row-sum epilogue.
// (unchanged from R14 — measured ~114us, near the FFMA2 issue floor)
__global__ __launch_bounds__(NTHREADS, 3)
void gemm_relu_rowsum_f32x2(const float* __restrict__ x1,
                            const float* __restrict__ x2,
                            const float* __restrict__ W1,
                            const float* __restrict__ W2) {
    extern __shared__ char smem[];
    float (*Xs)[TM][XPAD] = (float (*)[TM][XPAD])smem;                  // [2][128][36]
    float (*Ws)[TK][TN]   = (float (*)[TK][TN])(smem + 2 * XS_BYTES);   // [2][32][64]

    const int which = blockIdx.z;
    const float* __restrict__ X = which ? x2 : x1;
    const float* __restrict__ W = which ? W2 : W1;

    const int m0 = blockIdx.x * TM;
    const int n0 = blockIdx.y * TN;
    const int tid = threadIdx.x;
    const int tr = tid >> 3;   // 0..15 : row group (8 rows each)
    const int tc = tid & 7;    // 0..7  : col group (8 cols each)

    unsigned long long acc[8][4];     // [m][n-pair]
#pragma unroll
    for (int i = 0; i < 8; i++)
#pragma unroll
        for (int p = 0; p < 4; p++) acc[i][p] = 0ull;

    int xrowl[8], xchk[8];
    const float* xsrc0[8];
    int xsz[8];
#pragma unroll
    for (int q = 0; q < 8; q++) {
        int o = tid + q * NTHREADS;
        xrowl[q] = o >> 3;
        xchk[q] = o & 7;
        int gr = m0 + xrowl[q];
        bool v = gr < MTOT;
        xsrc0[q] = X + (size_t)(v ? gr : 0) * CDIM + xchk[q] * 4;
        xsz[q] = v ? 16 : 0;
    }

    // ---- prologue: cp.async tile 0 (X and W) ----
#pragma unroll
    for (int q = 0; q < 8; q++)
        cp_async16_zfill(smem_u32(&Xs[0][xrowl[q]][xchk[q] * 4]), xsrc0[q], xsz[q]);
#pragma unroll
    for (int q = 0; q < 4; q++) {
        int o = tid + q * NTHREADS;
        int k = o >> 4, n4 = (o & 15) * 4;
        cp_async16(smem_u32(&Ws[0][k][n4]), W + (size_t)k * HDIM + n0 + n4);
    }
    cp_async_commit();

    for (int kt = 0; kt < NKT; kt++) {
        const int buf = kt & 1;

        cp_async_wait0();     // tile kt landed (this thread's copies)
        __syncthreads();      // visible to all; compute(kt-1) finished

        // ---- issue cp.async tile kt+1 into buf^1 (overlaps compute) ----
        if (kt + 1 < NKT) {
            const int k0n = (kt + 1) * TK;
#pragma unroll
            for (int q = 0; q < 8; q++)
                cp_async16_zfill(smem_u32(&Xs[buf ^ 1][xrowl[q]][xchk[q] * 4]),
                                 xsrc0[q] + k0n, xsz[q]);
#pragma unroll
            for (int q = 0; q < 4; q++) {
                int o = tid + q * NTHREADS;
                int k = o >> 4, n4 = (o & 15) * 4;
                cp_async16(smem_u32(&Ws[buf ^ 1][k][n4]),
                           W + (size_t)(k0n + k) * HDIM + n0 + n4);
            }
            cp_async_commit();
        }

        // ---- compute: per k, 8 LDS.32 (A, bank-safe) + 2 LDS.128 (B) + 32 FFMA2 ----
        const float* xr0 = &Xs[buf][tr * 8][0];
#pragma unroll 4
        for (int kk = 0; kk < TK; kk++) {
            unsigned long long a2[8];
#pragma unroll
            for (int i = 0; i < 8; i++)
                a2[i] = dup2(xr0[i * XPAD + kk]);

            unsigned long long b2[4];
            {
                double2 t0 = *(const double2*)&Ws[buf][kk][tc * 8];
                double2 t1 = *(const double2*)&Ws[buf][kk][tc * 8 + 4];
                b2[0] = __double_as_longlong(t0.x);
                b2[1] = __double_as_longlong(t0.y);
                b2[2] = __double_as_longlong(t1.x);
                b2[3] = __double_as_longlong(t1.y);
            }
#pragma unroll
            for (int i = 0; i < 8; i++)
#pragma unroll
                for (int p = 0; p < 4; p++)
                    ffma2(acc[i][p], a2[i], b2[p]);
        }
    }

    // ---- unpack to scalar 8x8 (cols are natural pairs) ----
    float accf[8][8];
#pragma unroll
    for (int i = 0; i < 8; i++)
#pragma unroll
        for (int p = 0; p < 4; p++)
            unpack2(acc[i][p], accf[i][2 * p], accf[i][2 * p + 1]);

    // ---- epilogue: relu, group rows by batch, atomic into g_s ----
    const int rowbase = m0 + tr * 8;
    const int colbase = n0 + tc * 8;

    int i = 0;
    while (i < 8) {
        int gr = rowbase + i;
        if (gr >= MTOT) break;
        int b = gr / NROW;
        int bend = (b + 1) * NROW;
        float cs[8];
#pragma unroll
        for (int j = 0; j < 8; j++) cs[j] = 0.0f;
        while (i < 8 && (rowbase + i) < bend && (rowbase + i) < MTOT) {
#pragma unroll
            for (int j = 0; j < 8; j++) cs[j] += fmaxf(accf[i][j], 0.0f);
            i++;
        }
        float* dst = &g_s[which][b][colbase];
#pragma unroll
        for (int j = 0; j < 8; j++) atomicAdd(dst + j, cs[j]);
    }
}

// out[b,o] = sum_h s1[b,h]*s2[b,h]*Wp[h,o] + bp[o]*N1*N2
// 512 threads: 4-way h-split for MLP, smem tree reduce. Re-zeros g_s (block b
// exclusively owns slice b, so read-then-zero is race-free).
__global__ __launch_bounds__(512)
void final_kernel(const float* __restrict__ Wp,
                  const float* __restrict__ bp,
                  float* __restrict__ out) {
    const int b = blockIdx.x;
    const int t = threadIdx.x;

    __shared__ float sprod[HDIM];
    __shared__ float partial[4][ODIM];

    // Phase 1: sprod + zero (one element per thread)
    sprod[t] = g_s[0][b][t] * g_s[1][b][t];
    g_s[0][b][t] = 0.0f;
    g_s[1][b][t] = 0.0f;
    __syncthreads();

    // Phase 2: o = t&127, seg = t>>7 -> h in [seg*128, seg*128+128)
    const int o = t & (ODIM - 1);
    const int seg = t >> 7;
    const float* wp = Wp + (size_t)(seg * 128) * ODIM + o;
    const float* sp = &sprod[seg * 128];

    float acc = 0.0f;
#pragma unroll 16
    for (int h = 0; h < 128; h++)
        acc = fmaf(sp[h], wp[(size_t)h * ODIM], acc);
    partial[seg][o] = acc;
    __syncthreads();

    // Phase 3: reduce 4 segments, add bias
    if (t < ODIM) {
        float r = partial[0][t] + partial[1][t] + partial[2][t] + partial[3][t];
        out[b * ODIM + t] = r + bp[t] * (float)(NROW * NROW);
    }
}

extern "C" void kernel_launch(void* const* d_in, const int* in_sizes, int n_in,
                              void* d_out, int out_size) {
    const float* x1 = (const float*)d_in[0];
    const float* x2 = (const float*)d_in[1];
    const float* W1 = (const float*)d_in[2];
    const float* W2 = (const float*)d_in[3];
    const float* Wp = (const float*)d_in[4];
    const float* bp = (const float*)d_in[5];
    float* out = (float*)d_out;

    static bool attr_done = false;
    if (!attr_done) {
        cudaFuncSetAttribute(gemm_relu_rowsum_f32x2,
                             cudaFuncAttributeMaxDynamicSharedMemorySize, SMEM_SZ);
        attr_done = true;
    }

    gemm_relu_rowsum_f32x2<<<dim3(MTILES, NTILES, 2), NTHREADS, SMEM_SZ>>>(x1, x2, W1, W2);
    final_kernel<<<BATCH, 512>>>(Wp, bp, out);
}